// round 17
// baseline (speedup 1.0000x reference)
#include <cuda_runtime.h>
#include <cuda_bf16.h>
#include <math.h>
#include <stdint.h>

// Scratch histograms. Zero-initialized at load; entropy_kernel re-zeroes them
// after consuming, so every graph replay starts clean.
__device__ unsigned int g_hist[2][256];

#define HTHREADS 256
#define CHUNK_FLOATS 4096          // 16 KB chunks
#define CHUNK_F4     1024
#define CHUNK_BYTES  16384

struct __align__(128) HistSmem {
    float4 buf[2][CHUNK_F4];           // 32 KB double buffer (TMA dst)
    unsigned int hist[8][256];         // 8 KB per-warp histograms
    unsigned long long full[2];
    unsigned long long empty[2];
};

__device__ __forceinline__ uint32_t s2u(const void* p) {
    return (uint32_t)__cvta_generic_to_shared(p);
}
__device__ __forceinline__ void mbar_init(uint32_t a, uint32_t cnt) {
    asm volatile("mbarrier.init.shared.b64 [%0], %1;" :: "r"(a), "r"(cnt) : "memory");
}
__device__ __forceinline__ void mbar_expect_tx(uint32_t a, uint32_t bytes) {
    asm volatile("mbarrier.arrive.expect_tx.shared.b64 _, [%0], %1;" :: "r"(a), "r"(bytes) : "memory");
}
__device__ __forceinline__ void mbar_arrive(uint32_t a) {
    asm volatile("mbarrier.arrive.shared.b64 _, [%0];" :: "r"(a) : "memory");
}
__device__ __forceinline__ void mbar_wait(uint32_t a, uint32_t parity) {
    asm volatile("{\n\t"
        ".reg .pred P;\n\t"
        "LW_%=:\n\t"
        "mbarrier.try_wait.parity.acquire.cta.shared::cta.b64 P, [%0], %1, 0x989680;\n\t"
        "@P bra LD_%=;\n\t"
        "bra LW_%=;\n\t"
        "LD_%=:\n\t"
        "}" :: "r"(a), "r"(parity) : "memory");
}
__device__ __forceinline__ void bulk_g2s(uint32_t dst, const void* src,
                                         uint32_t bytes, uint32_t mbar) {
    asm volatile(
        "cp.async.bulk.shared::cluster.global.mbarrier::complete_tx::bytes "
        "[%0], [%1], %2, [%3];"
        :: "r"(dst), "l"(src), "r"(bytes), "r"(mbar) : "memory");
}

// Bit-exact binning (proven in R13): idx = clip(floor((x+1)*128), 0, 255),
// counted iff -1 <= x <= 1; add/mul unfused.
__device__ __forceinline__ void bin_one(float xv, unsigned int* __restrict__ h) {
    float s = __fadd_rn(xv, 1.0f);
    float t = __fmul_rn(s, 128.0f);
    int b = min(max(__float2int_rd(t), 0), 255);
    if (xv >= -1.0f && xv <= 1.0f) atomicAdd(&h[b], 1u);
}

// TMA double-buffered histogram. grid.y selects tensor.
__global__ __launch_bounds__(HTHREADS) void hist_kernel(
    const float* __restrict__ pred,
    const float* __restrict__ gt,
    int n)
{
    __shared__ HistSmem sm;
    const float* __restrict__ src = (blockIdx.y == 0) ? pred : gt;
    const int tid  = threadIdx.x;
    const int warp = tid >> 5;

    #pragma unroll
    for (int i = tid; i < 8 * 256; i += HTHREADS)
        ((unsigned int*)sm.hist)[i] = 0u;

    const uint32_t fullA[2]  = { s2u(&sm.full[0]),  s2u(&sm.full[1])  };
    const uint32_t emptyA[2] = { s2u(&sm.empty[0]), s2u(&sm.empty[1]) };
    if (tid == 0) {
        mbar_init(fullA[0], 1);        mbar_init(fullA[1], 1);
        mbar_init(emptyA[0], HTHREADS); mbar_init(emptyA[1], HTHREADS);
    }
    __syncthreads();

    const int n_chunks = n / CHUNK_FLOATS;
    int cnt = 0;
    if ((int)blockIdx.x < n_chunks)
        cnt = (n_chunks - blockIdx.x + gridDim.x - 1) / gridDim.x;

    // Prologue: fill both buffers.
    if (tid == 0) {
        if (cnt > 0) {
            mbar_expect_tx(fullA[0], CHUNK_BYTES);
            bulk_g2s(s2u(&sm.buf[0][0]),
                     src + (size_t)blockIdx.x * CHUNK_FLOATS,
                     CHUNK_BYTES, fullA[0]);
        }
        if (cnt > 1) {
            mbar_expect_tx(fullA[1], CHUNK_BYTES);
            bulk_g2s(s2u(&sm.buf[1][0]),
                     src + ((size_t)blockIdx.x + gridDim.x) * CHUNK_FLOATS,
                     CHUNK_BYTES, fullA[1]);
        }
    }

    unsigned int* __restrict__ h = sm.hist[warp];

    for (int i = 0; i < cnt; i++) {
        const int s = i & 1;
        const uint32_t par = (i >> 1) & 1;
        mbar_wait(fullA[s], par);

        #pragma unroll
        for (int k = 0; k < CHUNK_F4 / HTHREADS; k++) {      // 4 x LDS.128
            float4 v = sm.buf[s][tid + k * HTHREADS];
            bin_one(v.x, h);
            bin_one(v.y, h);
            bin_one(v.z, h);
            bin_one(v.w, h);
        }
        mbar_arrive(emptyA[s]);

        if (tid == 0 && i + 2 < cnt) {
            mbar_wait(emptyA[s], par);   // all 256 consumed buf s this cycle
            mbar_expect_tx(fullA[s], CHUNK_BYTES);
            bulk_g2s(s2u(&sm.buf[s][0]),
                     src + ((size_t)blockIdx.x + (size_t)(i + 2) * gridDim.x) * CHUNK_FLOATS,
                     CHUNK_BYTES, fullA[s]);
        }
    }

    // Tail (n % CHUNK_FLOATS, normally 0) — block 0 with plain loads.
    if (blockIdx.x == 0) {
        for (int idx = n_chunks * CHUNK_FLOATS + tid; idx < n; idx += HTHREADS)
            bin_one(src[idx], h);
    }

    __syncthreads();
    for (int bin = tid; bin < 256; bin += HTHREADS) {
        unsigned int sacc = 0;
        #pragma unroll
        for (int w = 0; w < 8; w++) sacc += sm.hist[w][bin];
        if (sacc) atomicAdd(&g_hist[blockIdx.y][bin], sacc);
    }
}

// XLA-CPU's vectorized f32 log (Cephes) with AArch64 FMA contraction.
// Verified bit-exact in R13.
__device__ __forceinline__ float cephes_logf_fma(float xin) {
    unsigned ux = __float_as_uint(xin);
    float e = (float)((int)(ux >> 23) - 126);
    float m = __uint_as_float((ux & 0x007fffffu) | 0x3f000000u);
    float x;
    if (m < 0.707106781186547524f) {
        e = __fadd_rn(e, -1.0f);
        x = __fadd_rn(__fadd_rn(m, -1.0f), m);
    } else {
        x = __fadd_rn(m, -1.0f);
    }
    float z = __fmul_rn(x, x);
    float y = 7.0376836292e-2f;
    y = fmaf(y, x, -1.1514610310e-1f);
    y = fmaf(y, x,  1.1676998740e-1f);
    y = fmaf(y, x, -1.2420140846e-1f);
    y = fmaf(y, x,  1.4249322787e-1f);
    y = fmaf(y, x, -1.6668057665e-1f);
    y = fmaf(y, x,  2.0000714765e-1f);
    y = fmaf(y, x, -2.4999993993e-1f);
    y = fmaf(y, x,  3.3333331174e-1f);
    y = __fmul_rn(y, x);
    y = __fmul_rn(y, z);
    y = fmaf(e, -2.12194440e-4f, y);
    y = fmaf(-0.5f, z, y);
    float r = __fadd_rn(x, y);
    r = fmaf(e, 0.693359375f, r);
    return r;
}

// Entropy epilogue (bit-identical to R13 serial): 256 threads compute (p, log p);
// thread 0 replays the exact VF4/IC1 fused-accumulate chain. Re-zeroes g_hist.
__global__ __launch_bounds__(256) void entropy_kernel(float* __restrict__ out) {
    __shared__ float sp[2][256];
    __shared__ float sl[2][256];
    __shared__ unsigned long long stot[2][8];

    const int t = threadIdx.x;
    const int warp = t >> 5, lane = t & 31;

    unsigned int c0 = g_hist[0][t];
    unsigned int c1 = g_hist[1][t];

    unsigned long long u0 = c0, u1 = c1;
    #pragma unroll
    for (int off = 16; off >= 1; off >>= 1) {
        u0 += __shfl_down_sync(0xffffffffu, u0, off);
        u1 += __shfl_down_sync(0xffffffffu, u1, off);
    }
    if (lane == 0) { stot[0][warp] = u0; stot[1][warp] = u1; }
    __syncthreads();

    unsigned long long tot0 = 0, tot1 = 0;
    #pragma unroll
    for (int w = 0; w < 8; w++) { tot0 += stot[0][w]; tot1 += stot[1][w]; }
    float T0 = (float)tot0;   // RNE of exact total
    float T1 = (float)tot1;

    {
        float p  = __fadd_rn(__fdiv_rn((float)c0, T0), 1e-8f);
        sp[0][t] = p;  sl[0][t] = cephes_logf_fma(p);
    }
    {
        float p  = __fadd_rn(__fdiv_rn((float)c1, T1), 1e-8f);
        sp[1][t] = p;  sl[1][t] = cephes_logf_fma(p);
    }

    g_hist[0][t] = 0u;
    g_hist[1][t] = 0u;
    __syncthreads();

    if (t == 0) {
        float H[2];
        #pragma unroll
        for (int j = 0; j < 2; j++) {
            float a0 = 0.0f, a1 = 0.0f, a2 = 0.0f, a3 = 0.0f;
            for (int k = 0; k < 64; k++) {
                a0 = fmaf(sp[j][4 * k + 0], sl[j][4 * k + 0], a0);
                a1 = fmaf(sp[j][4 * k + 1], sl[j][4 * k + 1], a1);
                a2 = fmaf(sp[j][4 * k + 2], sl[j][4 * k + 2], a2);
                a3 = fmaf(sp[j][4 * k + 3], sl[j][4 * k + 3], a3);
            }
            float S = __fadd_rn(__fadd_rn(a0, a1), __fadd_rn(a2, a3));
            H[j] = -S;
        }
        out[0] = fabsf(__fadd_rn(H[0], -H[1]));
    }
}

extern "C" void kernel_launch(void* const* d_in, const int* in_sizes, int n_in,
                              void* d_out, int out_size) {
    const float* pred = (const float*)d_in[0];
    const float* gt   = (const float*)d_in[1];
    float* out = (float*)d_out;

    int n = in_sizes[0];          // 33,554,432 per tensor

    dim3 grid(296, 2);            // 592 CTAs, ~4/SM, 40KB smem each
    hist_kernel<<<grid, HTHREADS>>>(pred, gt, n);

    entropy_kernel<<<1, 256>>>(out);
}